// round 13
// baseline (speedup 1.0000x reference)
#include <cuda_runtime.h>
#include <math.h>

// QuantumLayer: 4-qubit circuit, closed-form with phase folding.
//   z_q = R_q * cos(x_q - delta_q)
//   out0 = C0*c1c2c3, out1 = C1*c0c1, out2 = C2*c0c1c2, out3 = C3*c0c1c2c3
// Output layout: [NQ, B] float32, B = 1<<20 = 512*256*8 exactly.
//
// Each thread owns 2 quads (4 consecutive samples each) -> all stores are
// STG.128 (lane stride 16B, coalesced). All 8 sample loads are front-batched
// LDG.128 issued before the weight-constant init so DRAM latency overlaps
// the init trig + barrier.

#define TPB  256
#define GRID 512
#define NQUAD 2                         // quads per thread

__global__ __launch_bounds__(TPB)
void quantum_layer_kernel(const float* __restrict__ x,
                          const float* __restrict__ w,
                          float* __restrict__ out,
                          int B) {
    // Quad indices: lane-consecutive -> float4 stores coalesce.
    const unsigned q0 = blockIdx.x * (TPB * NQUAD) + threadIdx.x;  // quad A
    const unsigned q1 = q0 + TPB;                                  // quad B

    const float4* __restrict__ xv4 = reinterpret_cast<const float4*>(x);

    // ---- Front-batch all 8 sample loads (before init; MLP=8) ----
    float4 xa[4], xb[4];
#pragma unroll
    for (int j = 0; j < 4; ++j) xa[j] = xv4[4u * q0 + j];
#pragma unroll
    for (int j = 0; j < 4; ++j) xb[j] = xv4[4u * q1 + j];

    // ---- Weight-derived constants while loads are in flight ----
    __shared__ float sD[4];   // delta_q
    __shared__ float sR[4];   // R_q
    if (threadIdx.x < 4) {
        int q = threadIdx.x;
        float phi   = w[q * 3 + 0];
        float theta = w[q * 3 + 1];
        float st, ct;
        __sincosf(theta, &st, &ct);
        float kc = ct;
        float ks = -__cosf(phi) * st;
        sR[q] = sqrtf(kc * kc + ks * ks);
        sD[q] = atan2f(ks, kc);
    }
    __syncthreads();

    const float d0 = sD[0], d1 = sD[1], d2 = sD[2], d3 = sD[3];
    const float R0 = sR[0], R1 = sR[1], R2 = sR[2], R3 = sR[3];
    const float C1f = R0 * R1;
    const float C2f = C1f * R2;
    const float C3f = C2f * R3;
    const float C0f = R1 * R2 * R3;

    float4* __restrict__ o0 = reinterpret_cast<float4*>(out);
    float4* __restrict__ o1 = reinterpret_cast<float4*>(out + (unsigned)B);
    float4* __restrict__ o2 = reinterpret_cast<float4*>(out + 2u * (unsigned)B);
    float4* __restrict__ o3 = reinterpret_cast<float4*>(out + 3u * (unsigned)B);

#pragma unroll
    for (int g = 0; g < NQUAD; ++g) {
        const float4* xq = (g == 0) ? xa : xb;
        const unsigned qi = (g == 0) ? q0 : q1;

        float4 r0v, r1v, r2v, r3v;
        float* r0p = reinterpret_cast<float*>(&r0v);
        float* r1p = reinterpret_cast<float*>(&r1v);
        float* r2p = reinterpret_cast<float*>(&r2v);
        float* r3p = reinterpret_cast<float*>(&r3v);

#pragma unroll
        for (int j = 0; j < 4; ++j) {
            float c0 = __cosf(xq[j].x - d0);
            float c1 = __cosf(xq[j].y - d1);
            float c2 = __cosf(xq[j].z - d2);
            float c3 = __cosf(xq[j].w - d3);
            float a = c0 * c1;
            float b = c2 * c3;
            r0p[j] = C0f * (c1 * b);   // z1 z2 z3
            r1p[j] = C1f * a;          // z0 z1
            r2p[j] = C2f * (a * c2);   // z0 z1 z2
            r3p[j] = C3f * (a * b);    // z0 z1 z2 z3
        }

        // 4 x STG.128, lane stride 16B -> fully coalesced.
        o0[qi] = r0v;
        o1[qi] = r1v;
        o2[qi] = r2v;
        o3[qi] = r3v;
    }
}

extern "C" void kernel_launch(void* const* d_in, const int* in_sizes, int n_in,
                              void* d_out, int out_size) {
    const float* x = (const float*)d_in[0];   // inputs  [B, 4] float32
    const float* w = (const float*)d_in[1];   // weights [1, 4, 3] float32
    float* out = (float*)d_out;               // [4, B] float32

    int B = in_sizes[0] / 4;                  // 1<<20 = 512*256*8
    quantum_layer_kernel<<<GRID, TPB>>>(x, w, out, B);
}

// round 17
// speedup vs baseline: 1.1328x; 1.1328x over previous
#include <cuda_runtime.h>

// QuantumLayer: 4-qubit circuit, closed-form.
//   z_q  = kc_q*cos(x_q) + ks_q*sin(x_q),  kc=cos(theta), ks=-cos(phi)*sin(theta)
//   out0 = z1*z2*z3, out1 = z0*z1, out2 = z0*z1*z2, out3 = z0*z1*z2*z3
// Output layout: [NQ, B] float32, B = 1<<20 = 512*256*8 exactly.
//
// Best-measured shape (grid=512, TPB=256, 8 samples/thread, strided coalesced
// LDG.128 loads, streamed scalar STG.32 stores) with the init path stripped:
// NO shared memory, NO __syncthreads, NO atan2 -- every thread redundantly
// derives the 8 weight constants (broadcast loads + 8 MUFU) while its 8
// front-batched sample loads are in flight.

#define SAMP 8
#define TPB  256
#define GRID 512

__global__ __launch_bounds__(TPB)
void quantum_layer_kernel(const float* __restrict__ x,
                          const float* __restrict__ w,
                          float* __restrict__ out,
                          int B) {
    const unsigned i0 = blockIdx.x * (TPB * SAMP) + threadIdx.x;
    const float4* __restrict__ xin = reinterpret_cast<const float4*>(x) + i0;

    // ---- Front-batch all 8 sample loads (lane stride 16B, coalesced, MLP=8) ----
    float4 xv[SAMP];
#pragma unroll
    for (int j = 0; j < SAMP; ++j) xv[j] = xin[j * TPB];

    // ---- Per-thread weight constants (broadcast-address loads, overlaps xv) ----
    float kc[4], ks[4];
#pragma unroll
    for (int q = 0; q < 4; ++q) {
        float phi   = __ldg(&w[q * 3 + 0]);
        float theta = __ldg(&w[q * 3 + 1]);
        float st, ct;
        __sincosf(theta, &st, &ct);
        kc[q] = ct;
        ks[q] = -__cosf(phi) * st;
    }

    float* __restrict__ o0 = out + i0;
    float* __restrict__ o1 = o0 + (unsigned)B;
    float* __restrict__ o2 = o1 + (unsigned)B;
    float* __restrict__ o3 = o2 + (unsigned)B;

#pragma unroll
    for (int j = 0; j < SAMP; ++j) {
        float s, c;
        __sincosf(xv[j].x, &s, &c); float z0 = fmaf(kc[0], c, ks[0] * s);
        __sincosf(xv[j].y, &s, &c); float z1 = fmaf(kc[1], c, ks[1] * s);
        __sincosf(xv[j].z, &s, &c); float z2 = fmaf(kc[2], c, ks[2] * s);
        __sincosf(xv[j].w, &s, &c); float z3 = fmaf(kc[3], c, ks[3] * s);

        float a = z0 * z1;   // z0 z1
        float b = z2 * z3;   // z2 z3

        // Streamed scalar stores: lane stride 4B -> 1 line per STG.32.
        o0[j * TPB] = z1 * b;        // z1 z2 z3
        o1[j * TPB] = a;             // z0 z1
        o2[j * TPB] = a * z2;        // z0 z1 z2
        o3[j * TPB] = a * b;         // z0 z1 z2 z3
    }
}

extern "C" void kernel_launch(void* const* d_in, const int* in_sizes, int n_in,
                              void* d_out, int out_size) {
    const float* x = (const float*)d_in[0];   // inputs  [B, 4] float32
    const float* w = (const float*)d_in[1];   // weights [1, 4, 3] float32
    float* out = (float*)d_out;               // [4, B] float32

    int B = in_sizes[0] / 4;                  // 1<<20 = 512*256*8
    quantum_layer_kernel<<<GRID, TPB>>>(x, w, out, B);
}